// round 1
// baseline (speedup 1.0000x reference)
#include <cuda_runtime.h>
#include <cuda_bf16.h>
#include <cstdint>

// Problem dims (fixed)
#define T_STEPS 4
#define BATCH   16
#define NIMG    64          // T*B
#define CIN     256
#define CH      128
#define COUT    256
#define HDIM    56
#define HW      3136        // 56*56
#define EPSBN   1e-5f

// Scratch (allocation-free rule: __device__ globals)
__device__ float g_h1[(size_t)NIMG * CH * HW];     // 102.8 MB
__device__ float g_h2[(size_t)NIMG * CH * HW];     // 102.8 MB
__device__ float g_w2t[9 * CH * CH];               // transposed 3x3 weights [r][k][s][c]

// ---------------------------------------------------------------------------
// Weight transpose for conv2: w2[c][k][r][s] (OIHW) -> w2t[((r*128+k)*3+s)*128+c]
// Makes SMEM staging in conv2 fully coalesced.
// ---------------------------------------------------------------------------
__global__ void prep_w2t_kernel(const float* __restrict__ w2) {
    int d = blockIdx.x * blockDim.x + threadIdx.x;
    if (d >= 9 * CH * CH) return;
    int c = d & 127;
    int q = d >> 7;          // (r*128+k)*3+s
    int s = q % 3;
    int kq = q / 3;          // r*128+k
    int k = kq & 127;
    int r = kq >> 7;
    g_w2t[d] = w2[((c * CH + k) * 3 + r) * 3 + s];
}

// ---------------------------------------------------------------------------
// 1x1 conv + BN epilogue as batched GEMM.
// Y[img][c][hw] = BN( sum_k A[c][k] * X[img][k][hw] )
// Block: 128 (M) x 128 (N) tile, BK=16, 256 threads, 8x8 microtile.
// grid: (ceil(HW/128)=25, NIMG, Mtot/128)
// ---------------------------------------------------------------------------
__global__ __launch_bounds__(256) void gemm1x1_bn_kernel(
    const float* __restrict__ A,   // [Mtot, K] weights
    const float* __restrict__ X,   // [NIMG][K][HW]
    float* __restrict__ Y,         // [NIMG][Mtot][HW]
    int K, int Mtot,
    const float* __restrict__ gg, const float* __restrict__ bb,
    const float* __restrict__ mm, const float* __restrict__ vv)
{
    __shared__ float Asm[16][128];
    __shared__ float Bsm[16][128];

    const int hw0 = blockIdx.x * 128;
    const int img = blockIdx.y;
    const int cb  = blockIdx.z * 128;
    const int tid = threadIdx.x;

    float acc[8][8];
#pragma unroll
    for (int i = 0; i < 8; i++)
#pragma unroll
        for (int j = 0; j < 8; j++) acc[i][j] = 0.f;

    const float* Ximg = X + (size_t)img * K * HW;

    for (int k0 = 0; k0 < K; k0 += 16) {
        // stage A (128 c x 16 k), transposed into Asm[k][c]
#pragma unroll
        for (int j = 0; j < 2; j++) {
            int u  = tid + j * 256;          // 0..511 float4 units
            int c  = u >> 2;
            int kq = (u & 3) * 4;
            float4 a4 = *(const float4*)&A[(size_t)(cb + c) * K + k0 + kq];
            Asm[kq + 0][c] = a4.x;
            Asm[kq + 1][c] = a4.y;
            Asm[kq + 2][c] = a4.z;
            Asm[kq + 3][c] = a4.w;
        }
        // stage B (16 k x 128 hw)
#pragma unroll
        for (int j = 0; j < 2; j++) {
            int u  = tid + j * 256;
            int kk = u >> 5;
            int xq = (u & 31) * 4;
            float4 b4 = make_float4(0.f, 0.f, 0.f, 0.f);
            if (hw0 + xq < HW)
                b4 = *(const float4*)&Ximg[(size_t)(k0 + kk) * HW + hw0 + xq];
            *(float4*)&Bsm[kk][xq] = b4;
        }
        __syncthreads();

        const int c0 = (tid >> 4) * 8;
        const int x0 = (tid & 15) * 8;
#pragma unroll
        for (int kk = 0; kk < 16; kk++) {
            float av[8], bv[8];
            *(float4*)&av[0] = *(const float4*)&Asm[kk][c0];
            *(float4*)&av[4] = *(const float4*)&Asm[kk][c0 + 4];
            *(float4*)&bv[0] = *(const float4*)&Bsm[kk][x0];
            *(float4*)&bv[4] = *(const float4*)&Bsm[kk][x0 + 4];
#pragma unroll
            for (int i = 0; i < 8; i++)
#pragma unroll
                for (int j = 0; j < 8; j++)
                    acc[i][j] = fmaf(av[i], bv[j], acc[i][j]);
        }
        __syncthreads();
    }

    // epilogue: BN affine, bounds-checked store
    const int c0 = cb + (tid >> 4) * 8;
    const int x0 = hw0 + (tid & 15) * 8;
    float* Yimg = Y + (size_t)img * Mtot * HW;
#pragma unroll
    for (int i = 0; i < 8; i++) {
        int c = c0 + i;
        float sc = gg[c] / sqrtf(vv[c] + EPSBN);
        float bi = bb[c] - mm[c] * sc;
#pragma unroll
        for (int j = 0; j < 8; j++) {
            int x = x0 + j;
            if (x < HW) Yimg[(size_t)c * HW + x] = acc[i][j] * sc + bi;
        }
    }
}

// ---------------------------------------------------------------------------
// 3x3 conv (pad 1) + BN epilogue, implicit GEMM.
// Block = one output row (y) of one image: 128 out-ch x 56 x.
// 256 threads: thread = (cg 0..31, xg 0..7) -> 4 ch x 7 x outputs.
// K loop: r in 0..2 (input row), kc in 0..7 (16-channel chunks).
// Input row staged with x-halo; weight chunk staged from g_w2t (coalesced).
// ---------------------------------------------------------------------------
__global__ __launch_bounds__(256) void conv3x3_bn_kernel(
    const float* __restrict__ in,   // [NIMG][CH][HW]
    float* __restrict__ out,        // [NIMG][CH][HW]
    const float* __restrict__ gg, const float* __restrict__ bb,
    const float* __restrict__ mm, const float* __restrict__ vv)
{
    __shared__ float Asm[16 * 3 * 128];   // [kk][s][c]
    __shared__ float Bsm[16][58];         // [kk][x+1], x in -1..56

    const int y   = blockIdx.x;
    const int img = blockIdx.y;
    const int tid = threadIdx.x;
    const int cg = tid >> 3;      // 0..31
    const int xg = tid & 7;       // 0..7
    const int c0 = cg * 4;
    const int x0 = xg * 7;

    float acc[4][7];
#pragma unroll
    for (int i = 0; i < 4; i++)
#pragma unroll
        for (int j = 0; j < 7; j++) acc[i][j] = 0.f;

    const float* inimg = in + (size_t)img * CH * HW;

    for (int r = 0; r < 3; r++) {
        int yi = y + r - 1;
        if (yi < 0 || yi >= HDIM) continue;     // uniform across block
        for (int kc = 0; kc < 8; kc++) {
            __syncthreads();   // protect previous stage's reads
            // stage B: 16 ch x 58 (halo) input values of row yi
            for (int f = tid; f < 16 * 58; f += 256) {
                int kk = f / 58, xi = f % 58;
                int x = xi - 1;
                float val = 0.f;
                if (x >= 0 && x < HDIM)
                    val = inimg[(size_t)(kc * 16 + kk) * HW + yi * HDIM + x];
                Bsm[kk][xi] = val;
            }
            // stage A: 6144 floats, contiguous in g_w2t
            const float* wsrc = g_w2t + ((size_t)r * 128 + kc * 16) * 3 * 128;
            for (int f = tid; f < 1536; f += 256)
                *(float4*)&Asm[f * 4] = *(const float4*)&wsrc[f * 4];
            __syncthreads();

#pragma unroll
            for (int kk = 0; kk < 16; kk++) {
                float bv[9];
#pragma unroll
                for (int j = 0; j < 9; j++) bv[j] = Bsm[kk][x0 + j];
#pragma unroll
                for (int s = 0; s < 3; s++) {
                    float4 a4 = *(const float4*)&Asm[(kk * 3 + s) * 128 + c0];
                    float av[4] = {a4.x, a4.y, a4.z, a4.w};
#pragma unroll
                    for (int ci = 0; ci < 4; ci++)
#pragma unroll
                        for (int xi = 0; xi < 7; xi++)
                            acc[ci][xi] = fmaf(av[ci], bv[xi + s], acc[ci][xi]);
                }
            }
        }
    }

    // epilogue: BN
    float* outimg = out + (size_t)img * CH * HW;
#pragma unroll
    for (int ci = 0; ci < 4; ci++) {
        int c = c0 + ci;
        float sc = gg[c] / sqrtf(vv[c] + EPSBN);
        float bi = bb[c] - mm[c] * sc;
#pragma unroll
        for (int xi = 0; xi < 7; xi++)
            outimg[(size_t)c * HW + y * HDIM + x0 + xi] = acc[ci][xi] * sc + bi;
    }
}

// ---------------------------------------------------------------------------
// LIF over T in-place on d_out. v' = v + (h - v)*0.5; s = (v' >= 1); hard reset.
// ---------------------------------------------------------------------------
__global__ __launch_bounds__(256) void lif_kernel(float* __restrict__ out) {
    const size_t S4 = (size_t)BATCH * COUT * HW / 4;   // 3,211,264 float4 per t
    size_t j = (size_t)blockIdx.x * blockDim.x + threadIdx.x;
    if (j >= S4) return;
    float4* p = (float4*)out;
    float v[4] = {0.f, 0.f, 0.f, 0.f};
#pragma unroll
    for (int t = 0; t < T_STEPS; t++) {
        float4 h4 = p[(size_t)t * S4 + j];
        float hh[4] = {h4.x, h4.y, h4.z, h4.w};
        float ss[4];
#pragma unroll
        for (int l = 0; l < 4; l++) {
            v[l] = v[l] + (hh[l] - v[l]) * 0.5f;   // matches v + (x-v)/2 exactly
            float s = (v[l] >= 1.0f) ? 1.0f : 0.0f;
            ss[l] = s;
            v[l] *= (1.0f - s);
        }
        p[(size_t)t * S4 + j] = make_float4(ss[0], ss[1], ss[2], ss[3]);
    }
}

// ---------------------------------------------------------------------------
extern "C" void kernel_launch(void* const* d_in, const int* in_sizes, int n_in,
                              void* d_out, int out_size)
{
    const float* x  = (const float*)d_in[0];
    const float* w1 = (const float*)d_in[1];
    const float* g1 = (const float*)d_in[2];
    const float* b1 = (const float*)d_in[3];
    const float* m1 = (const float*)d_in[4];
    const float* v1 = (const float*)d_in[5];
    const float* w2 = (const float*)d_in[6];
    const float* g2 = (const float*)d_in[7];
    const float* b2 = (const float*)d_in[8];
    const float* m2 = (const float*)d_in[9];
    const float* v2 = (const float*)d_in[10];
    const float* w3 = (const float*)d_in[11];
    const float* g3 = (const float*)d_in[12];
    const float* b3 = (const float*)d_in[13];
    const float* m3 = (const float*)d_in[14];
    const float* v3 = (const float*)d_in[15];
    float* out = (float*)d_out;

    float *h1p, *h2p;
    cudaGetSymbolAddress((void**)&h1p, g_h1);
    cudaGetSymbolAddress((void**)&h2p, g_h2);

    // weight transform for conv2
    prep_w2t_kernel<<<(9 * CH * CH + 255) / 256, 256>>>(w2);

    // conv1: 1x1 256->128 + BN1
    gemm1x1_bn_kernel<<<dim3(25, NIMG, 1), 256>>>(w1, x, h1p, CIN, CH,
                                                  g1, b1, m1, v1);
    // conv2: 3x3 128->128 + BN2
    conv3x3_bn_kernel<<<dim3(HDIM, NIMG), 256>>>(h1p, h2p, g2, b2, m2, v2);

    // conv3: 1x1 128->256 + BN3, write directly to d_out
    gemm1x1_bn_kernel<<<dim3(25, NIMG, 2), 256>>>(w3, h2p, out, CH, COUT,
                                                  g3, b3, m3, v3);
    // LIF in-place
    lif_kernel<<<(int)(((size_t)BATCH * COUT * HW / 4 + 255) / 256), 256>>>(out);
}

// round 2
// speedup vs baseline: 1.0478x; 1.0478x over previous
#include <cuda_runtime.h>
#include <cuda_bf16.h>
#include <cstdint>

// Problem dims (fixed)
#define T_STEPS 4
#define BATCH   16
#define NIMG    64          // T*B
#define CIN     256
#define CH      128
#define COUT    256
#define HDIM    56
#define HW      3136        // 56*56
#define EPSBN   1e-5f

// Scratch (allocation-free rule: __device__ globals)
__device__ float g_h1[(size_t)NIMG * CH * HW];     // 102.8 MB
__device__ float g_h2[(size_t)NIMG * CH * HW];     // 102.8 MB
__device__ float g_w2t[9 * CH * CH];               // transposed 3x3 weights [r][k][s][c]

// ---------------- packed fp32x2 helpers (Blackwell FFMA2 path) ----------------
typedef unsigned long long u64;

__device__ __forceinline__ u64 dup2(float a) {
    u64 r; asm("mov.b64 %0, {%1, %1};" : "=l"(r) : "f"(a)); return r;
}
__device__ __forceinline__ void ffma2(u64& acc, u64 a, u64 b) {
    asm("fma.rn.f32x2 %0, %1, %2, %0;" : "+l"(acc) : "l"(a), "l"(b));
}
__device__ __forceinline__ float2 unpk(u64 v) {
    float2 f; asm("mov.b64 {%0, %1}, %2;" : "=f"(f.x), "=f"(f.y) : "l"(v)); return f;
}

// ---------------------------------------------------------------------------
// Weight transpose for conv2: w2[c][k][r][s] (OIHW) -> w2t[((r*128+k)*3+s)*128+c]
// ---------------------------------------------------------------------------
__global__ void prep_w2t_kernel(const float* __restrict__ w2) {
    int d = blockIdx.x * blockDim.x + threadIdx.x;
    if (d >= 9 * CH * CH) return;
    int c = d & 127;
    int q = d >> 7;          // (r*128+k)*3+s
    int s = q % 3;
    int kq = q / 3;          // r*128+k
    int k = kq & 127;
    int r = kq >> 7;
    g_w2t[d] = w2[((c * CH + k) * 3 + r) * 3 + s];
}

// ---------------------------------------------------------------------------
// 1x1 conv + BN epilogue as batched GEMM, packed fp32x2 inner product.
// Block: 128 (M=ch) x 128 (N=hw) tile, BK=32, 256 threads, 8x8 microtile
// (accumulators packed pairwise along hw -> bitwise identical to scalar FFMA).
// grid: (25, NIMG, Mtot/128)
// ---------------------------------------------------------------------------
__global__ __launch_bounds__(256, 2) void gemm1x1_bn_kernel(
    const float* __restrict__ A,   // [Mtot, K] weights
    const float* __restrict__ X,   // [NIMG][K][HW]
    float* __restrict__ Y,         // [NIMG][Mtot][HW]
    int K, int Mtot,
    const float* __restrict__ gg, const float* __restrict__ bb,
    const float* __restrict__ mm, const float* __restrict__ vv)
{
    __shared__ float Asm[32][128];
    __shared__ float Bsm[32][128];

    const int hw0 = blockIdx.x * 128;
    const int img = blockIdx.y;
    const int cb  = blockIdx.z * 128;
    const int tid = threadIdx.x;

    u64 acc2[8][4];
#pragma unroll
    for (int i = 0; i < 8; i++)
#pragma unroll
        for (int j = 0; j < 4; j++) acc2[i][j] = 0ull;

    const float* Ximg = X + (size_t)img * K * HW;

    for (int k0 = 0; k0 < K; k0 += 32) {
        // stage A (128 c x 32 k), transposed into Asm[k][c]
#pragma unroll
        for (int j = 0; j < 4; j++) {
            int u  = tid + j * 256;          // 0..1023 float4 units
            int c  = u >> 3;                 // 8 float4 per channel row
            int kq = (u & 7) * 4;
            float4 a4 = *(const float4*)&A[(size_t)(cb + c) * K + k0 + kq];
            Asm[kq + 0][c] = a4.x;
            Asm[kq + 1][c] = a4.y;
            Asm[kq + 2][c] = a4.z;
            Asm[kq + 3][c] = a4.w;
        }
        // stage B (32 k x 128 hw)
#pragma unroll
        for (int j = 0; j < 4; j++) {
            int u  = tid + j * 256;
            int kk = u >> 5;
            int xq = (u & 31) * 4;
            float4 b4 = make_float4(0.f, 0.f, 0.f, 0.f);
            if (hw0 + xq < HW)
                b4 = *(const float4*)&Ximg[(size_t)(k0 + kk) * HW + hw0 + xq];
            *(float4*)&Bsm[kk][xq] = b4;
        }
        __syncthreads();

        const int c0 = (tid >> 4) * 8;
        const int x0 = (tid & 15) * 8;
#pragma unroll 8
        for (int kk = 0; kk < 32; kk++) {
            float av[8];
            *(float4*)&av[0] = *(const float4*)&Asm[kk][c0];
            *(float4*)&av[4] = *(const float4*)&Asm[kk][c0 + 4];
            u64 bv2[4];
            const u64* bp = (const u64*)&Bsm[kk][x0];
            bv2[0] = bp[0]; bv2[1] = bp[1]; bv2[2] = bp[2]; bv2[3] = bp[3];
#pragma unroll
            for (int i = 0; i < 8; i++) {
                u64 a2 = dup2(av[i]);
                ffma2(acc2[i][0], a2, bv2[0]);
                ffma2(acc2[i][1], a2, bv2[1]);
                ffma2(acc2[i][2], a2, bv2[2]);
                ffma2(acc2[i][3], a2, bv2[3]);
            }
        }
        __syncthreads();
    }

    // epilogue: BN affine, bounds-checked store
    const int c0 = cb + (tid >> 4) * 8;
    const int x0 = hw0 + (tid & 15) * 8;
    float* Yimg = Y + (size_t)img * Mtot * HW;
#pragma unroll
    for (int i = 0; i < 8; i++) {
        int c = c0 + i;
        float sc = gg[c] / sqrtf(vv[c] + EPSBN);
        float bi = bb[c] - mm[c] * sc;
#pragma unroll
        for (int j = 0; j < 4; j++) {
            float2 v2 = unpk(acc2[i][j]);
            int x = x0 + 2 * j;
            if (x < HW)     Yimg[(size_t)c * HW + x]     = v2.x * sc + bi;
            if (x + 1 < HW) Yimg[(size_t)c * HW + x + 1] = v2.y * sc + bi;
        }
    }
}

// ---------------------------------------------------------------------------
// 3x3 conv (pad 1) + BN epilogue, implicit GEMM, packed fp32x2.
// Block = one output row (y) of one image: 128 out-ch x 56 x.
// thread = (cg 0..31, xg 0..7) -> 4 ch x 7 x outputs; accumulators packed
// pairwise along channels (independent accumulators -> bitwise identical).
// ---------------------------------------------------------------------------
__global__ __launch_bounds__(256) void conv3x3_bn_kernel(
    const float* __restrict__ in,   // [NIMG][CH][HW]
    float* __restrict__ out,        // [NIMG][CH][HW]
    const float* __restrict__ gg, const float* __restrict__ bb,
    const float* __restrict__ mm, const float* __restrict__ vv)
{
    __shared__ float Asm[16 * 3 * 128];   // [kk][s][c]
    __shared__ float Bsm[16][58];         // [kk][x+1], x in -1..56

    const int y   = blockIdx.x;
    const int img = blockIdx.y;
    const int tid = threadIdx.x;
    const int cg = tid >> 3;      // 0..31
    const int xg = tid & 7;       // 0..7
    const int c0 = cg * 4;
    const int x0 = xg * 7;

    u64 acc2[2][7];               // [channel pair][x]
#pragma unroll
    for (int i = 0; i < 2; i++)
#pragma unroll
        for (int j = 0; j < 7; j++) acc2[i][j] = 0ull;

    const float* inimg = in + (size_t)img * CH * HW;

    for (int r = 0; r < 3; r++) {
        int yi = y + r - 1;
        if (yi < 0 || yi >= HDIM) continue;     // uniform across block
        for (int kc = 0; kc < 8; kc++) {
            __syncthreads();   // protect previous stage's reads
            // stage B: 16 ch x 58 (halo) input values of row yi
            for (int f = tid; f < 16 * 58; f += 256) {
                int kk = f / 58, xi = f % 58;
                int x = xi - 1;
                float val = 0.f;
                if (x >= 0 && x < HDIM)
                    val = inimg[(size_t)(kc * 16 + kk) * HW + yi * HDIM + x];
                Bsm[kk][xi] = val;
            }
            // stage A: 6144 floats, contiguous in g_w2t
            const float* wsrc = g_w2t + ((size_t)r * 128 + kc * 16) * 3 * 128;
            for (int f = tid; f < 1536; f += 256)
                *(float4*)&Asm[f * 4] = *(const float4*)&wsrc[f * 4];
            __syncthreads();

#pragma unroll
            for (int kk = 0; kk < 16; kk++) {
                u64 bd[9];
#pragma unroll
                for (int j = 0; j < 9; j++) bd[j] = dup2(Bsm[kk][x0 + j]);
#pragma unroll
                for (int s = 0; s < 3; s++) {
                    const u64* ap = (const u64*)&Asm[(kk * 3 + s) * 128 + c0];
                    u64 a0 = ap[0], a1 = ap[1];   // (c0,c0+1), (c0+2,c0+3)
#pragma unroll
                    for (int xi = 0; xi < 7; xi++) {
                        ffma2(acc2[0][xi], a0, bd[xi + s]);
                        ffma2(acc2[1][xi], a1, bd[xi + s]);
                    }
                }
            }
        }
    }

    // epilogue: BN
    float* outimg = out + (size_t)img * CH * HW;
#pragma unroll
    for (int i = 0; i < 2; i++) {
#pragma unroll
        for (int l = 0; l < 2; l++) {
            int c = c0 + i * 2 + l;
            float sc = gg[c] / sqrtf(vv[c] + EPSBN);
            float bi = bb[c] - mm[c] * sc;
#pragma unroll
            for (int xi = 0; xi < 7; xi++) {
                float2 v2 = unpk(acc2[i][xi]);
                float v = (l == 0) ? v2.x : v2.y;
                outimg[(size_t)c * HW + y * HDIM + x0 + xi] = v * sc + bi;
            }
        }
    }
}

// ---------------------------------------------------------------------------
// LIF over T in-place on d_out. v' = v + (h - v)*0.5; s = (v' >= 1); hard reset.
// ---------------------------------------------------------------------------
__global__ __launch_bounds__(256) void lif_kernel(float* __restrict__ out) {
    const size_t S4 = (size_t)BATCH * COUT * HW / 4;   // float4 per timestep
    size_t j = (size_t)blockIdx.x * blockDim.x + threadIdx.x;
    if (j >= S4) return;
    float4* p = (float4*)out;
    float v[4] = {0.f, 0.f, 0.f, 0.f};
#pragma unroll
    for (int t = 0; t < T_STEPS; t++) {
        float4 h4 = p[(size_t)t * S4 + j];
        float hh[4] = {h4.x, h4.y, h4.z, h4.w};
        float ss[4];
#pragma unroll
        for (int l = 0; l < 4; l++) {
            v[l] = v[l] + (hh[l] - v[l]) * 0.5f;   // matches v + (x-v)/2 exactly
            float s = (v[l] >= 1.0f) ? 1.0f : 0.0f;
            ss[l] = s;
            v[l] *= (1.0f - s);
        }
        p[(size_t)t * S4 + j] = make_float4(ss[0], ss[1], ss[2], ss[3]);
    }
}

// ---------------------------------------------------------------------------
extern "C" void kernel_launch(void* const* d_in, const int* in_sizes, int n_in,
                              void* d_out, int out_size)
{
    const float* x  = (const float*)d_in[0];
    const float* w1 = (const float*)d_in[1];
    const float* g1 = (const float*)d_in[2];
    const float* b1 = (const float*)d_in[3];
    const float* m1 = (const float*)d_in[4];
    const float* v1 = (const float*)d_in[5];
    const float* w2 = (const float*)d_in[6];
    const float* g2 = (const float*)d_in[7];
    const float* b2 = (const float*)d_in[8];
    const float* m2 = (const float*)d_in[9];
    const float* v2 = (const float*)d_in[10];
    const float* w3 = (const float*)d_in[11];
    const float* g3 = (const float*)d_in[12];
    const float* b3 = (const float*)d_in[13];
    const float* m3 = (const float*)d_in[14];
    const float* v3 = (const float*)d_in[15];
    float* out = (float*)d_out;

    float *h1p, *h2p;
    cudaGetSymbolAddress((void**)&h1p, g_h1);
    cudaGetSymbolAddress((void**)&h2p, g_h2);

    // weight transform for conv2
    prep_w2t_kernel<<<(9 * CH * CH + 255) / 256, 256>>>(w2);

    // conv1: 1x1 256->128 + BN1
    gemm1x1_bn_kernel<<<dim3(25, NIMG, 1), 256>>>(w1, x, h1p, CIN, CH,
                                                  g1, b1, m1, v1);
    // conv2: 3x3 128->128 + BN2
    conv3x3_bn_kernel<<<dim3(HDIM, NIMG), 256>>>(h1p, h2p, g2, b2, m2, v2);

    // conv3: 1x1 128->256 + BN3, write directly to d_out
    gemm1x1_bn_kernel<<<dim3(25, NIMG, 2), 256>>>(w3, h2p, out, CH, COUT,
                                                  g3, b3, m3, v3);
    // LIF in-place
    lif_kernel<<<(int)(((size_t)BATCH * COUT * HW / 4 + 255) / 256), 256>>>(out);
}

// round 5
// speedup vs baseline: 1.2185x; 1.1629x over previous
#include <cuda_runtime.h>
#include <cuda_bf16.h>
#include <cstdint>

// Problem dims (fixed)
#define T_STEPS 4
#define BATCH   16
#define NIMG    64          // T*B
#define CIN     256
#define CH      128
#define COUT    256
#define HDIM    56
#define HW      3136        // 56*56
#define EPSBN   1e-5f

typedef unsigned long long u64;
typedef unsigned int u32;

// ------------------------- device scratch (no malloc allowed) ---------------
#define HSPLIT ((size_t)NIMG * HW * 128)           // elements per split tensor
__device__ __nv_bfloat16 g_h1s[3 * HSPLIT];        // h1 bf16 splits, channel-last: [j][img][y][x][c]
__device__ float g_h2[(size_t)NIMG * CH * HW];     // conv2 output fp32 [img][c][hw]
// w2 bf16 splits: [rs 9][split 3][kh 2][m 128][64 halves]
__device__ __nv_bfloat16 g_w2a[9 * 3 * 2 * 128 * 64];

// ---------------- packed fp32x2 helpers (for 1x1 fp32 GEMMs) ----------------
__device__ __forceinline__ u64 dup2(float a) {
    u64 r; asm("mov.b64 %0, {%1, %1};" : "=l"(r) : "f"(a)); return r;
}
__device__ __forceinline__ void ffma2(u64& acc, u64 a, u64 b) {
    asm("fma.rn.f32x2 %0, %1, %2, %0;" : "+l"(acc) : "l"(a), "l"(b));
}
__device__ __forceinline__ float2 unpk(u64 v) {
    float2 f; asm("mov.b64 {%0, %1}, %2;" : "=f"(f.x), "=f"(f.y) : "l"(v)); return f;
}

// ---------------------------- mma.sync helpers ------------------------------
__device__ __forceinline__ u32 smem_u32(const void* p) {
    u32 a; asm("{ .reg .u64 t; cvta.to.shared.u64 t, %1; cvt.u32.u64 %0, t; }" : "=r"(a) : "l"(p));
    return a;
}
__device__ __forceinline__ void ldm4(u32* r, u32 addr) {
    asm volatile("ldmatrix.sync.aligned.m8n8.x4.shared.b16 {%0,%1,%2,%3}, [%4];"
        : "=r"(r[0]), "=r"(r[1]), "=r"(r[2]), "=r"(r[3]) : "r"(addr));
}
__device__ __forceinline__ void ldm2(u32* r, u32 addr) {
    asm volatile("ldmatrix.sync.aligned.m8n8.x2.shared.b16 {%0,%1}, [%2];"
        : "=r"(r[0]), "=r"(r[1]) : "r"(addr));
}
__device__ __forceinline__ void mma16816(float* d, const u32* a, const u32* b) {
    asm volatile("mma.sync.aligned.m16n8k16.row.col.f32.bf16.bf16.f32 "
        "{%0,%1,%2,%3}, {%4,%5,%6,%7}, {%8,%9}, {%0,%1,%2,%3};"
        : "+f"(d[0]), "+f"(d[1]), "+f"(d[2]), "+f"(d[3])
        : "r"(a[0]), "r"(a[1]), "r"(a[2]), "r"(a[3]), "r"(b[0]), "r"(b[1]));
}
__device__ __forceinline__ void cp16(u32 dst, const void* src, bool valid) {
    int sz = valid ? 16 : 0;
    asm volatile("cp.async.cg.shared.global [%0], [%1], 16, %2;"
                 :: "r"(dst), "l"(src), "r"(sz) : "memory");
}
__device__ __forceinline__ void cp_commit() {
    asm volatile("cp.async.commit_group;" ::: "memory");
}
__device__ __forceinline__ void cp_wait0() {
    asm volatile("cp.async.wait_group 0;" ::: "memory");
}

// ---------------------------------------------------------------------------
// prep: w2 (OIHW [128][128][3][3]) -> bf16x3 splits [rs][split][kh][m][64]
// ---------------------------------------------------------------------------
__global__ void prep_w2a_kernel(const float* __restrict__ w2) {
    int idx = blockIdx.x * blockDim.x + threadIdx.x;
    if (idx >= 9 * 128 * 128) return;
    int k = idx & 127;
    int m = (idx >> 7) & 127;
    int rs = idx >> 14;
    float w = w2[((size_t)(m * 128 + k)) * 9 + rs];
    __nv_bfloat16 b0 = __float2bfloat16_rn(w);
    float r1 = w - __bfloat162float(b0);
    __nv_bfloat16 b1 = __float2bfloat16_rn(r1);
    float r2 = r1 - __bfloat162float(b1);
    __nv_bfloat16 b2 = __float2bfloat16_rn(r2);
    int kh = k >> 6, ko = k & 63;
    size_t base = ((((size_t)rs * 3) * 2 + kh) * 128 + m) * 64 + ko;
    size_t sstep = (size_t)2 * 128 * 64;   // stride between splits
    g_w2a[base]             = b0;
    g_w2a[base + sstep]     = b1;
    g_w2a[base + 2 * sstep] = b2;
}

// ---------------------------------------------------------------------------
// conv1: 1x1 256->128 + BN, fp32 GEMM; epilogue writes bf16x3 channel-last.
// ---------------------------------------------------------------------------
__global__ __launch_bounds__(256, 2) void conv1_kernel(
    const float* __restrict__ A,   // w1 [128,256]
    const float* __restrict__ X,   // x  [NIMG][256][HW]
    const float* __restrict__ gg, const float* __restrict__ bb,
    const float* __restrict__ mm, const float* __restrict__ vv)
{
    __shared__ float Asm[32][128];
    __shared__ float Bsm[32][128];
    const int K = CIN;
    const int hw0 = blockIdx.x * 128;
    const int img = blockIdx.y;
    const int tid = threadIdx.x;

    u64 acc2[8][4];
#pragma unroll
    for (int i = 0; i < 8; i++)
#pragma unroll
        for (int j = 0; j < 4; j++) acc2[i][j] = 0ull;

    const float* Ximg = X + (size_t)img * K * HW;

    for (int k0 = 0; k0 < K; k0 += 32) {
#pragma unroll
        for (int j = 0; j < 4; j++) {
            int u = tid + j * 256;
            int c = u >> 3;
            int kq = (u & 7) * 4;
            float4 a4 = *(const float4*)&A[(size_t)c * K + k0 + kq];
            Asm[kq + 0][c] = a4.x; Asm[kq + 1][c] = a4.y;
            Asm[kq + 2][c] = a4.z; Asm[kq + 3][c] = a4.w;
        }
#pragma unroll
        for (int j = 0; j < 4; j++) {
            int u = tid + j * 256;
            int kk = u >> 5;
            int xq = (u & 31) * 4;
            float4 b4 = make_float4(0.f, 0.f, 0.f, 0.f);
            if (hw0 + xq < HW)
                b4 = *(const float4*)&Ximg[(size_t)(k0 + kk) * HW + hw0 + xq];
            *(float4*)&Bsm[kk][xq] = b4;
        }
        __syncthreads();
        const int c0 = (tid >> 4) * 8;
        const int x0 = (tid & 15) * 8;
#pragma unroll 8
        for (int kk = 0; kk < 32; kk++) {
            float av[8];
            *(float4*)&av[0] = *(const float4*)&Asm[kk][c0];
            *(float4*)&av[4] = *(const float4*)&Asm[kk][c0 + 4];
            u64 bv2[4];
            const u64* bp = (const u64*)&Bsm[kk][x0];
            bv2[0] = bp[0]; bv2[1] = bp[1]; bv2[2] = bp[2]; bv2[3] = bp[3];
#pragma unroll
            for (int i = 0; i < 8; i++) {
                u64 a2 = dup2(av[i]);
                ffma2(acc2[i][0], a2, bv2[0]);
                ffma2(acc2[i][1], a2, bv2[1]);
                ffma2(acc2[i][2], a2, bv2[2]);
                ffma2(acc2[i][3], a2, bv2[3]);
            }
        }
        __syncthreads();
    }

    const int c0 = (tid >> 4) * 8;
    const int x0 = (tid & 15) * 8;
    float sc[8], bi[8];
#pragma unroll
    for (int i = 0; i < 8; i++) {
        int c = c0 + i;
        sc[i] = gg[c] / sqrtf(vv[c] + EPSBN);
        bi[i] = bb[c] - mm[c] * sc[i];
    }
#pragma unroll
    for (int j = 0; j < 8; j++) {
        int pos = hw0 + x0 + j;
        if (pos >= HW) continue;
        unsigned short p0[8], p1[8], p2[8];
#pragma unroll
        for (int i = 0; i < 8; i++) {
            float2 v2 = unpk(acc2[i][j >> 1]);
            float h = ((j & 1) ? v2.y : v2.x) * sc[i] + bi[i];
            __nv_bfloat16 b0 = __float2bfloat16_rn(h);
            float r1 = h - __bfloat162float(b0);
            __nv_bfloat16 b1 = __float2bfloat16_rn(r1);
            float r2 = r1 - __bfloat162float(b1);
            __nv_bfloat16 b2 = __float2bfloat16_rn(r2);
            p0[i] = *(unsigned short*)&b0;
            p1[i] = *(unsigned short*)&b1;
            p2[i] = *(unsigned short*)&b2;
        }
        size_t base = ((size_t)img * HW + pos) * 128 + c0;
        *(uint4*)&g_h1s[base]              = *(uint4*)p0;
        *(uint4*)&g_h1s[HSPLIT + base]     = *(uint4*)p1;
        *(uint4*)&g_h1s[2 * HSPLIT + base] = *(uint4*)p2;
    }
}

// ---------------------------------------------------------------------------
// conv2: 3x3 128->128 + BN via mma.sync bf16x3, Ootomo accumulation discipline:
//  - main a0b0 term: HMMA chains of one tap (4 mmas), flushed to fp32 totals
//  - corrections (a0b1,a0b2,a1b0,a1b1,a2b0): separate HMMA accumulator
//    (magnitude ~2^-9 -> RZ bias negligible), flushed once per k-half.
// Block = (img, 2 output rows). 8 warps = 4 M x 2 rows. Warp tile M32 x N56.
// B (3 splits, 4 input rows w/ y-halo, 58 px w/ x-halo, 64ch half) staged per
// k-half; 3x3 shift is pure smem offset addressing. A tiles double-buffered.
// Per kh: 36 A-tile phases: [a0 main x9][a0 corr x9][a1 corr x9][a2 corr x9].
// ---------------------------------------------------------------------------
#define BSTR 144                      // bytes per pixel entry (64 halves + pad)
#define SB_ROW (58 * BSTR)            // 8352
#define SB_SPLIT_SZ (4 * SB_ROW)      // 33408
#define A_OFF (3 * SB_SPLIT_SZ)       // 100224 (16B aligned)
#define A_BUFSZ (128 * BSTR)          // 18432
#define SMEM_CONV2 (A_OFF + 2 * A_BUFSZ)   // 137088

__device__ __forceinline__ void sched36(int it, int& split, int& tap, int& bjs, int& nbj) {
    if (it < 9)       { split = 0; tap = it;      bjs = 0; nbj = 1; }   // main
    else if (it < 18) { split = 0; tap = it - 9;  bjs = 1; nbj = 2; }   // a0b1, a0b2
    else if (it < 27) { split = 1; tap = it - 18; bjs = 0; nbj = 2; }   // a1b0, a1b1
    else              { split = 2; tap = it - 27; bjs = 0; nbj = 1; }   // a2b0
}

__global__ __launch_bounds__(256) void conv2_hmma_kernel(
    const float* __restrict__ gg, const float* __restrict__ bb,
    const float* __restrict__ mm, const float* __restrict__ vv)
{
    extern __shared__ char smem[];
    const u32 sb = smem_u32(smem);
    const int tid = threadIdx.x;
    const int wid = tid >> 5;
    const int lane = tid & 31;
    const int img = blockIdx.y;
    const int y0 = blockIdx.x * 2;
    const int m0 = (wid & 3) * 32;    // warp M offset
    const int nw = wid >> 2;          // warp output row (0 or 1)

    float totals[2][7][4];
    float work[2][7][4];
#pragma unroll
    for (int a = 0; a < 2; a++)
#pragma unroll
        for (int n = 0; n < 7; n++)
#pragma unroll
            for (int d = 0; d < 4; d++) { totals[a][n][d] = 0.f; work[a][n][d] = 0.f; }

    // ldmatrix per-lane address terms
    const u32 aLane = (u32)(((lane & 7) + (lane & 8)) * BSTR + ((lane >> 4) & 1) * 16);
    const u32 bLane = (u32)((lane & 7) * BSTR + ((lane >> 3) & 1) * 16);

    for (int kh = 0; kh < 2; kh++) {
        // ---- stage B: 3 splits x 4 input rows x 58 px x 64 halves ----
        for (int f = tid; f < 3 * 4 * 58 * 8; f += 256) {
            int q = f & 7;
            int p = f >> 3;           // 0..695
            int px = p % 58;
            int t = p / 58;           // 0..11
            int ri = t & 3;
            int split = t >> 2;
            int y = y0 - 1 + ri;
            int x = px - 1;
            bool valid = ((unsigned)y < (unsigned)HDIM) && ((unsigned)x < (unsigned)HDIM);
            u32 dst = sb + split * SB_SPLIT_SZ + ri * SB_ROW + px * BSTR + q * 16;
            const char* src = (const char*)g_h1s +
                (((size_t)split * HSPLIT +
                  (((size_t)img * HW + (valid ? (y * HDIM + x) : 0)) * 128 + kh * 64 + q * 8)) << 1);
            cp16(dst, src, valid);
        }
        cp_commit();
        // ---- load A tile for it=0 (split0, tap0) ----
        {
            const char* tbase = (const char*)g_w2a + ((size_t)((0 * 3 + 0) * 2 + kh) * 8192) * 2;
#pragma unroll
            for (int q = 0; q < 4; q++) {
                int f = tid + q * 256;
                cp16(sb + A_OFF + (f >> 3) * BSTR + (f & 7) * 16, tbase + (size_t)f * 16, true);
            }
            cp_commit();
        }
        cp_wait0();
        __syncthreads();

#pragma unroll 1
        for (int it = 0; it < 36; it++) {
            // prefetch next A tile into other buffer
            if (it < 35) {
                int nsplit, ntap, nbjs, nnbj;
                sched36(it + 1, nsplit, ntap, nbjs, nnbj);
                const char* tbase = (const char*)g_w2a +
                    ((size_t)((ntap * 3 + nsplit) * 2 + kh) * 8192) * 2;
                u32 abase = sb + A_OFF + ((it + 1) & 1) * A_BUFSZ;
#pragma unroll
                for (int q = 0; q < 4; q++) {
                    int f = tid + q * 256;
                    cp16(abase + (f >> 3) * BSTR + (f & 7) * 16, tbase + (size_t)f * 16, true);
                }
                cp_commit();
            }
            int split, tap, bjs, nbj;
            sched36(it, split, tap, bjs, nbj);
            const int r = tap / 3;
            const int s = tap - r * 3;
            const int ri = nw + r;                 // input row index in staged B
            const u32 ab = sb + A_OFF + (it & 1) * A_BUFSZ;

#pragma unroll
            for (int ks = 0; ks < 4; ks++) {
                u32 afr[2][4];
                ldm4(afr[0], ab + (u32)(m0 * BSTR) + aLane + ks * 32);
                ldm4(afr[1], ab + (u32)((m0 + 16) * BSTR) + aLane + ks * 32);
#pragma unroll 1
                for (int j = 0; j < nbj; j++) {
                    const u32 bbase = sb + (bjs + j) * SB_SPLIT_SZ + ri * SB_ROW
                                      + (u32)(ks * 32) + bLane;
#pragma unroll
                    for (int nt = 0; nt < 7; nt++) {
                        u32 bfr[2];
                        ldm2(bfr, bbase + (nt * 8 + s) * BSTR);
                        mma16816(work[0][nt], afr[0], bfr);
                        mma16816(work[1][nt], afr[1], bfr);
                    }
                }
            }
            cp_wait0();
            __syncthreads();
            // flush: per tap during main phase; once at end for corrections
            if (it < 9 || it == 35) {
#pragma unroll
                for (int a = 0; a < 2; a++)
#pragma unroll
                    for (int n = 0; n < 7; n++)
#pragma unroll
                        for (int d = 0; d < 4; d++) {
                            totals[a][n][d] += work[a][n][d];
                            work[a][n][d] = 0.f;
                        }
            }
        }
    }

    // ---- epilogue: BN + store to g_h2 [img][c][hw] ----
    const int g = lane >> 2;
    const int t2 = lane & 3;
    float scv[2][2], biv[2][2];
#pragma unroll
    for (int mt = 0; mt < 2; mt++)
#pragma unroll
        for (int h = 0; h < 2; h++) {
            int c = m0 + mt * 16 + g + h * 8;
            float sc = gg[c] / sqrtf(vv[c] + EPSBN);
            scv[mt][h] = sc;
            biv[mt][h] = bb[c] - mm[c] * sc;
        }
    float* outimg = g_h2 + (size_t)img * CH * HW;
    const int yo = y0 + nw;
#pragma unroll
    for (int nt = 0; nt < 7; nt++) {
        int xo = nt * 8 + 2 * t2;
#pragma unroll
        for (int mt = 0; mt < 2; mt++) {
            int clo = m0 + mt * 16 + g;
            float2 vlo = make_float2(totals[mt][nt][0] * scv[mt][0] + biv[mt][0],
                                     totals[mt][nt][1] * scv[mt][0] + biv[mt][0]);
            float2 vhi = make_float2(totals[mt][nt][2] * scv[mt][1] + biv[mt][1],
                                     totals[mt][nt][3] * scv[mt][1] + biv[mt][1]);
            *(float2*)&outimg[(size_t)clo * HW + yo * HDIM + xo] = vlo;
            *(float2*)&outimg[(size_t)(clo + 8) * HW + yo * HDIM + xo] = vhi;
        }
    }
}

// ---------------------------------------------------------------------------
// conv3: 1x1 128->256 + BN, fp32 GEMM, writes d_out fp32.
// ---------------------------------------------------------------------------
__global__ __launch_bounds__(256, 2) void gemm1x1_bn_kernel(
    const float* __restrict__ A, const float* __restrict__ X, float* __restrict__ Y,
    int K, int Mtot,
    const float* __restrict__ gg, const float* __restrict__ bb,
    const float* __restrict__ mm, const float* __restrict__ vv)
{
    __shared__ float Asm[32][128];
    __shared__ float Bsm[32][128];
    const int hw0 = blockIdx.x * 128;
    const int img = blockIdx.y;
    const int cb  = blockIdx.z * 128;
    const int tid = threadIdx.x;

    u64 acc2[8][4];
#pragma unroll
    for (int i = 0; i < 8; i++)
#pragma unroll
        for (int j = 0; j < 4; j++) acc2[i][j] = 0ull;

    const float* Ximg = X + (size_t)img * K * HW;

    for (int k0 = 0; k0 < K; k0 += 32) {
#pragma unroll
        for (int j = 0; j < 4; j++) {
            int u = tid + j * 256;
            int c = u >> 3;
            int kq = (u & 7) * 4;
            float4 a4 = *(const float4*)&A[(size_t)(cb + c) * K + k0 + kq];
            Asm[kq + 0][c] = a4.x; Asm[kq + 1][c] = a4.y;
            Asm[kq + 2][c] = a4.z; Asm[kq + 3][c] = a4.w;
        }
#pragma unroll
        for (int j = 0; j < 4; j++) {
            int u = tid + j * 256;
            int kk = u >> 5;
            int xq = (u & 31) * 4;
            float4 b4 = make_float4(0.f, 0.f, 0.f, 0.f);
            if (hw0 + xq < HW)
                b4 = *(const float4*)&Ximg[(size_t)(k0 + kk) * HW + hw0 + xq];
            *(float4*)&Bsm[kk][xq] = b4;
        }
        __syncthreads();
        const int c0 = (tid >> 4) * 8;
        const int x0 = (tid & 15) * 8;
#pragma unroll 8
        for (int kk = 0; kk < 32; kk++) {
            float av[8];
            *(float4*)&av[0] = *(const float4*)&Asm[kk][c0];
            *(float4*)&av[4] = *(const float4*)&Asm[kk][c0 + 4];
            u64 bv2[4];
            const u64* bp = (const u64*)&Bsm[kk][x0];
            bv2[0] = bp[0]; bv2[1] = bp[1]; bv2[2] = bp[2]; bv2[3] = bp[3];
#pragma unroll
            for (int i = 0; i < 8; i++) {
                u64 a2 = dup2(av[i]);
                ffma2(acc2[i][0], a2, bv2[0]);
                ffma2(acc2[i][1], a2, bv2[1]);
                ffma2(acc2[i][2], a2, bv2[2]);
                ffma2(acc2[i][3], a2, bv2[3]);
            }
        }
        __syncthreads();
    }

    const int c0 = cb + (tid >> 4) * 8;
    const int x0 = hw0 + (tid & 15) * 8;
    float* Yimg = Y + (size_t)img * Mtot * HW;
#pragma unroll
    for (int i = 0; i < 8; i++) {
        int c = c0 + i;
        float sc = gg[c] / sqrtf(vv[c] + EPSBN);
        float bi = bb[c] - mm[c] * sc;
#pragma unroll
        for (int j = 0; j < 4; j++) {
            float2 v2 = unpk(acc2[i][j]);
            int x = x0 + 2 * j;
            if (x < HW)     Yimg[(size_t)c * HW + x]     = v2.x * sc + bi;
            if (x + 1 < HW) Yimg[(size_t)c * HW + x + 1] = v2.y * sc + bi;
        }
    }
}

// ---------------------------------------------------------------------------
// LIF over T in-place on d_out.
// ---------------------------------------------------------------------------
__global__ __launch_bounds__(256) void lif_kernel(float* __restrict__ out) {
    const size_t S4 = (size_t)BATCH * COUT * HW / 4;
    size_t j = (size_t)blockIdx.x * blockDim.x + threadIdx.x;
    if (j >= S4) return;
    float4* p = (float4*)out;
    float v[4] = {0.f, 0.f, 0.f, 0.f};
#pragma unroll
    for (int t = 0; t < T_STEPS; t++) {
        float4 h4 = p[(size_t)t * S4 + j];
        float hh[4] = {h4.x, h4.y, h4.z, h4.w};
        float ss[4];
#pragma unroll
        for (int l = 0; l < 4; l++) {
            v[l] = v[l] + (hh[l] - v[l]) * 0.5f;
            float s = (v[l] >= 1.0f) ? 1.0f : 0.0f;
            ss[l] = s;
            v[l] *= (1.0f - s);
        }
        p[(size_t)t * S4 + j] = make_float4(ss[0], ss[1], ss[2], ss[3]);
    }
}

// ---------------------------------------------------------------------------
extern "C" void kernel_launch(void* const* d_in, const int* in_sizes, int n_in,
                              void* d_out, int out_size)
{
    const float* x  = (const float*)d_in[0];
    const float* w1 = (const float*)d_in[1];
    const float* g1 = (const float*)d_in[2];
    const float* b1 = (const float*)d_in[3];
    const float* m1 = (const float*)d_in[4];
    const float* v1 = (const float*)d_in[5];
    const float* w2 = (const float*)d_in[6];
    const float* g2 = (const float*)d_in[7];
    const float* b2 = (const float*)d_in[8];
    const float* m2 = (const float*)d_in[9];
    const float* v2 = (const float*)d_in[10];
    const float* w3 = (const float*)d_in[11];
    const float* g3 = (const float*)d_in[12];
    const float* b3 = (const float*)d_in[13];
    const float* m3 = (const float*)d_in[14];
    const float* v3 = (const float*)d_in[15];
    float* out = (float*)d_out;

    float* h2p;
    cudaGetSymbolAddress((void**)&h2p, g_h2);

    cudaFuncSetAttribute(conv2_hmma_kernel,
                         cudaFuncAttributeMaxDynamicSharedMemorySize, SMEM_CONV2);

    // weight split for conv2
    prep_w2a_kernel<<<(9 * 128 * 128 + 255) / 256, 256>>>(w2);

    // conv1: 1x1 256->128 + BN1 -> bf16x3 channel-last splits
    conv1_kernel<<<dim3(25, NIMG), 256>>>(w1, x, g1, b1, m1, v1);

    // conv2: 3x3 128->128 + BN2 via mma.sync (Ootomo-disciplined bf16x3)
    conv2_hmma_kernel<<<dim3(28, NIMG), 256, SMEM_CONV2>>>(g2, b2, m2, v2);

    // conv3: 1x1 128->256 + BN3 -> d_out
    gemm1x1_bn_kernel<<<dim3(25, NIMG, 2), 256>>>(w3, h2p, out, CH, COUT,
                                                  g3, b3, m3, v3);
    // LIF in-place
    lif_kernel<<<(int)(((size_t)BATCH * COUT * HW / 4 + 255) / 256), 256>>>(out);
}

// round 6
// speedup vs baseline: 1.2735x; 1.0451x over previous
#include <cuda_runtime.h>
#include <cuda_bf16.h>
#include <cstdint>

// Problem dims (fixed)
#define T_STEPS 4
#define BATCH   16
#define NIMG    64          // T*B
#define CIN     256
#define CH      128
#define COUT    256
#define HDIM    56
#define HW      3136        // 56*56
#define EPSBN   1e-5f

typedef unsigned long long u64;
typedef unsigned int u32;
typedef unsigned short u16;

// ------------------------- device scratch (no malloc allowed) ---------------
#define HSPLIT ((size_t)NIMG * HW * 128)           // elements per split tensor
__device__ __nv_bfloat16 g_h1s[3 * HSPLIT];        // h1 bf16 splits, channel-last
__device__ float g_h2[(size_t)NIMG * CH * HW];     // conv2 output fp32 [img][c][hw]
// w2 bf16 splits: [rs 9][split 3][kh 2][m 128][64 halves]
__device__ __nv_bfloat16 g_w2a[9 * 3 * 2 * 128 * 64];
// w3 bf16 splits: [cb 2][split 3][kh 2][m 128][64 halves]
__device__ __nv_bfloat16 g_w3s[2 * 3 * 2 * 128 * 64];

// ---------------- packed fp32x2 helpers (for conv1 fp32 GEMM) ---------------
__device__ __forceinline__ u64 dup2(float a) {
    u64 r; asm("mov.b64 %0, {%1, %1};" : "=l"(r) : "f"(a)); return r;
}
__device__ __forceinline__ void ffma2(u64& acc, u64 a, u64 b) {
    asm("fma.rn.f32x2 %0, %1, %2, %0;" : "+l"(acc) : "l"(a), "l"(b));
}
__device__ __forceinline__ float2 unpk(u64 v) {
    float2 f; asm("mov.b64 {%0, %1}, %2;" : "=f"(f.x), "=f"(f.y) : "l"(v)); return f;
}

// ---------------------------- mma.sync helpers ------------------------------
__device__ __forceinline__ u32 smem_u32(const void* p) {
    u32 a; asm("{ .reg .u64 t; cvta.to.shared.u64 t, %1; cvt.u32.u64 %0, t; }" : "=r"(a) : "l"(p));
    return a;
}
__device__ __forceinline__ void ldm4(u32* r, u32 addr) {
    asm volatile("ldmatrix.sync.aligned.m8n8.x4.shared.b16 {%0,%1,%2,%3}, [%4];"
        : "=r"(r[0]), "=r"(r[1]), "=r"(r[2]), "=r"(r[3]) : "r"(addr));
}
__device__ __forceinline__ void ldm2(u32* r, u32 addr) {
    asm volatile("ldmatrix.sync.aligned.m8n8.x2.shared.b16 {%0,%1}, [%2];"
        : "=r"(r[0]), "=r"(r[1]) : "r"(addr));
}
__device__ __forceinline__ void mma16816(float* d, const u32* a, const u32* b) {
    asm volatile("mma.sync.aligned.m16n8k16.row.col.f32.bf16.bf16.f32 "
        "{%0,%1,%2,%3}, {%4,%5,%6,%7}, {%8,%9}, {%0,%1,%2,%3};"
        : "+f"(d[0]), "+f"(d[1]), "+f"(d[2]), "+f"(d[3])
        : "r"(a[0]), "r"(a[1]), "r"(a[2]), "r"(a[3]), "r"(b[0]), "r"(b[1]));
}
__device__ __forceinline__ void cp16(u32 dst, const void* src, bool valid) {
    int sz = valid ? 16 : 0;
    asm volatile("cp.async.cg.shared.global [%0], [%1], 16, %2;"
                 :: "r"(dst), "l"(src), "r"(sz) : "memory");
}
__device__ __forceinline__ void cp_commit() {
    asm volatile("cp.async.commit_group;" ::: "memory");
}
__device__ __forceinline__ void cp_wait0() {
    asm volatile("cp.async.wait_group 0;" ::: "memory");
}

// ---------------------------------------------------------------------------
// prep: w2 (OIHW [128][128][3][3]) -> bf16x3 splits [rs][split][kh][m][64]
// ---------------------------------------------------------------------------
__global__ void prep_w2a_kernel(const float* __restrict__ w2) {
    int idx = blockIdx.x * blockDim.x + threadIdx.x;
    if (idx >= 9 * 128 * 128) return;
    int k = idx & 127;
    int m = (idx >> 7) & 127;
    int rs = idx >> 14;
    float w = w2[((size_t)(m * 128 + k)) * 9 + rs];
    __nv_bfloat16 b0 = __float2bfloat16_rn(w);
    float r1 = w - __bfloat162float(b0);
    __nv_bfloat16 b1 = __float2bfloat16_rn(r1);
    float r2 = r1 - __bfloat162float(b1);
    __nv_bfloat16 b2 = __float2bfloat16_rn(r2);
    int kh = k >> 6, ko = k & 63;
    size_t base = ((((size_t)rs * 3) * 2 + kh) * 128 + m) * 64 + ko;
    size_t sstep = (size_t)2 * 128 * 64;   // stride between splits
    g_w2a[base]             = b0;
    g_w2a[base + sstep]     = b1;
    g_w2a[base + 2 * sstep] = b2;
}

// ---------------------------------------------------------------------------
// prep: w3 ([256][128]) -> bf16x3 splits [cb 2][split 3][kh 2][m 128][64]
// ---------------------------------------------------------------------------
__global__ void prep_w3s_kernel(const float* __restrict__ w3) {
    int idx = blockIdx.x * blockDim.x + threadIdx.x;
    if (idx >= 256 * 128) return;
    int k = idx & 127;
    int mg = idx >> 7;            // 0..255
    int cb = mg >> 7, m = mg & 127;
    float w = w3[(size_t)mg * 128 + k];
    __nv_bfloat16 b0 = __float2bfloat16_rn(w);
    float r1 = w - __bfloat162float(b0);
    __nv_bfloat16 b1 = __float2bfloat16_rn(r1);
    float r2 = r1 - __bfloat162float(b1);
    __nv_bfloat16 b2 = __float2bfloat16_rn(r2);
    int kh = k >> 6, ko = k & 63;
    size_t sstep = (size_t)2 * 128 * 64;
    size_t base = ((((size_t)cb * 3) * 2 + kh) * 128 + m) * 64 + ko;
    g_w3s[base]             = b0;
    g_w3s[base + sstep]     = b1;
    g_w3s[base + 2 * sstep] = b2;
}

// ---------------------------------------------------------------------------
// conv1: 1x1 256->128 + BN, fp32 GEMM; epilogue writes bf16x3 channel-last.
// ---------------------------------------------------------------------------
__global__ __launch_bounds__(256, 2) void conv1_kernel(
    const float* __restrict__ A,   // w1 [128,256]
    const float* __restrict__ X,   // x  [NIMG][256][HW]
    const float* __restrict__ gg, const float* __restrict__ bb,
    const float* __restrict__ mm, const float* __restrict__ vv)
{
    __shared__ float Asm[32][128];
    __shared__ float Bsm[32][128];
    const int K = CIN;
    const int hw0 = blockIdx.x * 128;
    const int img = blockIdx.y;
    const int tid = threadIdx.x;

    u64 acc2[8][4];
#pragma unroll
    for (int i = 0; i < 8; i++)
#pragma unroll
        for (int j = 0; j < 4; j++) acc2[i][j] = 0ull;

    const float* Ximg = X + (size_t)img * K * HW;

    for (int k0 = 0; k0 < K; k0 += 32) {
#pragma unroll
        for (int j = 0; j < 4; j++) {
            int u = tid + j * 256;
            int c = u >> 3;
            int kq = (u & 7) * 4;
            float4 a4 = *(const float4*)&A[(size_t)c * K + k0 + kq];
            Asm[kq + 0][c] = a4.x; Asm[kq + 1][c] = a4.y;
            Asm[kq + 2][c] = a4.z; Asm[kq + 3][c] = a4.w;
        }
#pragma unroll
        for (int j = 0; j < 4; j++) {
            int u = tid + j * 256;
            int kk = u >> 5;
            int xq = (u & 31) * 4;
            float4 b4 = make_float4(0.f, 0.f, 0.f, 0.f);
            if (hw0 + xq < HW)
                b4 = *(const float4*)&Ximg[(size_t)(k0 + kk) * HW + hw0 + xq];
            *(float4*)&Bsm[kk][xq] = b4;
        }
        __syncthreads();
        const int c0 = (tid >> 4) * 8;
        const int x0 = (tid & 15) * 8;
#pragma unroll 8
        for (int kk = 0; kk < 32; kk++) {
            float av[8];
            *(float4*)&av[0] = *(const float4*)&Asm[kk][c0];
            *(float4*)&av[4] = *(const float4*)&Asm[kk][c0 + 4];
            u64 bv2[4];
            const u64* bp = (const u64*)&Bsm[kk][x0];
            bv2[0] = bp[0]; bv2[1] = bp[1]; bv2[2] = bp[2]; bv2[3] = bp[3];
#pragma unroll
            for (int i = 0; i < 8; i++) {
                u64 a2 = dup2(av[i]);
                ffma2(acc2[i][0], a2, bv2[0]);
                ffma2(acc2[i][1], a2, bv2[1]);
                ffma2(acc2[i][2], a2, bv2[2]);
                ffma2(acc2[i][3], a2, bv2[3]);
            }
        }
        __syncthreads();
    }

    const int c0 = (tid >> 4) * 8;
    const int x0 = (tid & 15) * 8;
    float sc[8], bi[8];
#pragma unroll
    for (int i = 0; i < 8; i++) {
        int c = c0 + i;
        sc[i] = gg[c] / sqrtf(vv[c] + EPSBN);
        bi[i] = bb[c] - mm[c] * sc[i];
    }
#pragma unroll
    for (int j = 0; j < 8; j++) {
        int pos = hw0 + x0 + j;
        if (pos >= HW) continue;
        u16 p0[8], p1[8], p2[8];
#pragma unroll
        for (int i = 0; i < 8; i++) {
            float2 v2 = unpk(acc2[i][j >> 1]);
            float h = ((j & 1) ? v2.y : v2.x) * sc[i] + bi[i];
            __nv_bfloat16 b0 = __float2bfloat16_rn(h);
            float r1 = h - __bfloat162float(b0);
            __nv_bfloat16 b1 = __float2bfloat16_rn(r1);
            float r2 = r1 - __bfloat162float(b1);
            __nv_bfloat16 b2 = __float2bfloat16_rn(r2);
            p0[i] = *(u16*)&b0;
            p1[i] = *(u16*)&b1;
            p2[i] = *(u16*)&b2;
        }
        size_t base = ((size_t)img * HW + pos) * 128 + c0;
        *(uint4*)&g_h1s[base]              = *(uint4*)p0;
        *(uint4*)&g_h1s[HSPLIT + base]     = *(uint4*)p1;
        *(uint4*)&g_h1s[2 * HSPLIT + base] = *(uint4*)p2;
    }
}

// ---------------------------------------------------------------------------
// conv2: 3x3 128->128 + BN via mma.sync bf16x3 (Ootomo discipline). Unchanged
// from round 5 (passed, rel_err 6.3e-4).
// ---------------------------------------------------------------------------
#define BSTR 144                      // bytes per pixel entry (64 halves + pad)
#define SB_ROW (58 * BSTR)            // 8352
#define SB_SPLIT_SZ (4 * SB_ROW)      // 33408
#define A_OFF (3 * SB_SPLIT_SZ)       // 100224 (16B aligned)
#define A_BUFSZ (128 * BSTR)          // 18432
#define SMEM_CONV2 (A_OFF + 2 * A_BUFSZ)   // 137088

__device__ __forceinline__ void sched36(int it, int& split, int& tap, int& bjs, int& nbj) {
    if (it < 9)       { split = 0; tap = it;      bjs = 0; nbj = 1; }   // main
    else if (it < 18) { split = 0; tap = it - 9;  bjs = 1; nbj = 2; }   // a0b1, a0b2
    else if (it < 27) { split = 1; tap = it - 18; bjs = 0; nbj = 2; }   // a1b0, a1b1
    else              { split = 2; tap = it - 27; bjs = 0; nbj = 1; }   // a2b0
}

__global__ __launch_bounds__(256) void conv2_hmma_kernel(
    const float* __restrict__ gg, const float* __restrict__ bb,
    const float* __restrict__ mm, const float* __restrict__ vv)
{
    extern __shared__ char smem[];
    const u32 sb = smem_u32(smem);
    const int tid = threadIdx.x;
    const int wid = tid >> 5;
    const int lane = tid & 31;
    const int img = blockIdx.y;
    const int y0 = blockIdx.x * 2;
    const int m0 = (wid & 3) * 32;    // warp M offset
    const int nw = wid >> 2;          // warp output row (0 or 1)

    float totals[2][7][4];
    float work[2][7][4];
#pragma unroll
    for (int a = 0; a < 2; a++)
#pragma unroll
        for (int n = 0; n < 7; n++)
#pragma unroll
            for (int d = 0; d < 4; d++) { totals[a][n][d] = 0.f; work[a][n][d] = 0.f; }

    const u32 aLane = (u32)(((lane & 7) + (lane & 8)) * BSTR + ((lane >> 4) & 1) * 16);
    const u32 bLane = (u32)((lane & 7) * BSTR + ((lane >> 3) & 1) * 16);

    for (int kh = 0; kh < 2; kh++) {
        // ---- stage B: 3 splits x 4 input rows x 58 px x 64 halves ----
        for (int f = tid; f < 3 * 4 * 58 * 8; f += 256) {
            int q = f & 7;
            int p = f >> 3;
            int px = p % 58;
            int t = p / 58;
            int ri = t & 3;
            int split = t >> 2;
            int y = y0 - 1 + ri;
            int x = px - 1;
            bool valid = ((unsigned)y < (unsigned)HDIM) && ((unsigned)x < (unsigned)HDIM);
            u32 dst = sb + split * SB_SPLIT_SZ + ri * SB_ROW + px * BSTR + q * 16;
            const char* src = (const char*)g_h1s +
                (((size_t)split * HSPLIT +
                  (((size_t)img * HW + (valid ? (y * HDIM + x) : 0)) * 128 + kh * 64 + q * 8)) << 1);
            cp16(dst, src, valid);
        }
        cp_commit();
        {
            const char* tbase = (const char*)g_w2a + ((size_t)(0 * 3 + 0) * 2 + kh) * 8192 * 2;
#pragma unroll
            for (int q = 0; q < 4; q++) {
                int f = tid + q * 256;
                cp16(sb + A_OFF + (f >> 3) * BSTR + (f & 7) * 16, tbase + (size_t)f * 16, true);
            }
            cp_commit();
        }
        cp_wait0();
        __syncthreads();

#pragma unroll 1
        for (int it = 0; it < 36; it++) {
            if (it < 35) {
                int nsplit, ntap, nbjs, nnbj;
                sched36(it + 1, nsplit, ntap, nbjs, nnbj);
                const char* tbase = (const char*)g_w2a +
                    ((size_t)((ntap * 3 + nsplit) * 2 + kh) * 8192) * 2;
                u32 abase = sb + A_OFF + ((it + 1) & 1) * A_BUFSZ;
#pragma unroll
                for (int q = 0; q < 4; q++) {
                    int f = tid + q * 256;
                    cp16(abase + (f >> 3) * BSTR + (f & 7) * 16, tbase + (size_t)f * 16, true);
                }
                cp_commit();
            }
            int split, tap, bjs, nbj;
            sched36(it, split, tap, bjs, nbj);
            const int r = tap / 3;
            const int s = tap - r * 3;
            const int ri = nw + r;
            const u32 ab = sb + A_OFF + (it & 1) * A_BUFSZ;

#pragma unroll
            for (int ks = 0; ks < 4; ks++) {
                u32 afr[2][4];
                ldm4(afr[0], ab + (u32)(m0 * BSTR) + aLane + ks * 32);
                ldm4(afr[1], ab + (u32)((m0 + 16) * BSTR) + aLane + ks * 32);
#pragma unroll 1
                for (int j = 0; j < nbj; j++) {
                    const u32 bbase = sb + (bjs + j) * SB_SPLIT_SZ + ri * SB_ROW
                                      + (u32)(ks * 32) + bLane;
#pragma unroll
                    for (int nt = 0; nt < 7; nt++) {
                        u32 bfr[2];
                        ldm2(bfr, bbase + (nt * 8 + s) * BSTR);
                        mma16816(work[0][nt], afr[0], bfr);
                        mma16816(work[1][nt], afr[1], bfr);
                    }
                }
            }
            cp_wait0();
            __syncthreads();
            if (it < 9 || it == 35) {
#pragma unroll
                for (int a = 0; a < 2; a++)
#pragma unroll
                    for (int n = 0; n < 7; n++)
#pragma unroll
                        for (int d = 0; d < 4; d++) {
                            totals[a][n][d] += work[a][n][d];
                            work[a][n][d] = 0.f;
                        }
            }
        }
    }

    // ---- epilogue: BN + store fp32 to g_h2 [img][c][hw] ----
    const int g = lane >> 2;
    const int t2 = lane & 3;
    float scv[2][2], biv[2][2];
#pragma unroll
    for (int mt = 0; mt < 2; mt++)
#pragma unroll
        for (int h = 0; h < 2; h++) {
            int c = m0 + mt * 16 + g + h * 8;
            float sc = gg[c] / sqrtf(vv[c] + EPSBN);
            scv[mt][h] = sc;
            biv[mt][h] = bb[c] - mm[c] * sc;
        }
    float* outimg = g_h2 + (size_t)img * CH * HW;
    const int yo = y0 + nw;
#pragma unroll
    for (int nt = 0; nt < 7; nt++) {
        int xo = nt * 8 + 2 * t2;
#pragma unroll
        for (int mt = 0; mt < 2; mt++) {
            int clo = m0 + mt * 16 + g;
            float2 vlo = make_float2(totals[mt][nt][0] * scv[mt][0] + biv[mt][0],
                                     totals[mt][nt][1] * scv[mt][0] + biv[mt][0]);
            float2 vhi = make_float2(totals[mt][nt][2] * scv[mt][1] + biv[mt][1],
                                     totals[mt][nt][3] * scv[mt][1] + biv[mt][1]);
            *(float2*)&outimg[(size_t)clo * HW + yo * HDIM + xo] = vlo;
            *(float2*)&outimg[(size_t)(clo + 8) * HW + yo * HDIM + xo] = vhi;
        }
    }
}

// ---------------------------------------------------------------------------
// conv3 + BN + LIF fused, via mma.sync bf16x3 (corrections-first single-acc).
// grid (49 hw-tiles of 64 px, 16 batch, 2 cb). 256 thr = 8 warps (4M x 2N).
// Loops t=0..3 over timesteps (img = t*16+b), LIF state in registers.
// A (w3 splits) staged once via cp.async. B (h2 fp32) loaded per t, split
// to bf16x3 in-kernel via XOR-swizzled fp32 smem staging (conflict-free).
// ---------------------------------------------------------------------------
#define C3_A_SPLIT 36864      // 2*128*144
#define C3_A_KH    18432
#define C3_B_OFF   110592
#define C3_B_SPLIT 18432      // 2*64*144
#define C3_B_KH    9216
#define C3_F_OFF   165888     // fp32 staging, 32KB, xor-swizzled float4s
#define SMEM_CONV3 (C3_F_OFF + 32768)   // 198656

__global__ __launch_bounds__(256) void conv3_lif_kernel(
    const float* __restrict__ gg, const float* __restrict__ bb,
    const float* __restrict__ mm, const float* __restrict__ vv,
    float* __restrict__ out)
{
    extern __shared__ char smem[];
    const u32 sb = smem_u32(smem);
    const int tid = threadIdx.x;
    const int wid = tid >> 5;
    const int lane = tid & 31;
    const int hw0 = blockIdx.x * 64;
    const int bidx = blockIdx.y;
    const int cb = blockIdx.z;
    const int m0 = (wid & 3) * 32;
    const int n0 = (wid >> 2) * 32;

    // ---- stage A once: 3 splits x 2 kh x 128 m x 128B (144B stride) ----
    for (int f = tid; f < 6912; f += 256) {
        int q = f & 7;
        int row = f >> 3;              // 0..863
        int m = row & 127;
        int kh = (row >> 7) & 1;
        int split = row >> 8;
        u32 dst = sb + split * C3_A_SPLIT + kh * C3_A_KH + m * BSTR + q * 16;
        const char* src = (const char*)g_w3s +
            ((((size_t)(cb * 3 + split) * 2 + kh) * 128 + m) * 128 + q * 16);
        cp16(dst, src, true);
    }
    cp_commit();

    const u32 aLane = (u32)(((lane & 7) + (lane & 8)) * BSTR + ((lane >> 4) & 1) * 16);
    const u32 bLane = (u32)((lane & 7) * BSTR + ((lane >> 3) & 1) * 16);
    const int g = lane >> 2;
    const int t2 = lane & 3;

    // BN constants (output channels of this block)
    float scv[2][2], biv[2][2];
#pragma unroll
    for (int mt = 0; mt < 2; mt++)
#pragma unroll
        for (int h = 0; h < 2; h++) {
            int c = cb * 128 + m0 + mt * 16 + g + h * 8;
            float sc = gg[c] / sqrtf(vv[c] + EPSBN);
            scv[mt][h] = sc;
            biv[mt][h] = bb[c] - mm[c] * sc;
        }

    // LIF membrane state
    float vst[2][4][4];
#pragma unroll
    for (int a = 0; a < 2; a++)
#pragma unroll
        for (int n = 0; n < 4; n++)
#pragma unroll
            for (int d = 0; d < 4; d++) vst[a][n][d] = 0.f;

    // combo order: corrections first (acc small -> RZ harmless), main last
    const int AI[6] = {0, 0, 1, 1, 2, 0};
    const int BJ[6] = {1, 2, 0, 1, 0, 0};

#pragma unroll 1
    for (int t = 0; t < T_STEPS; t++) {
        const int img = t * BATCH + bidx;
        __syncthreads();   // protect B smem from previous iteration's reads

        // ---- load h2 fp32 tile [k=128][px=64] into xor-swizzled staging ----
#pragma unroll
        for (int q = 0; q < 8; q++) {
            int f = tid + q * 256;
            int k = f >> 4, c4 = f & 15;
            float4 v4 = *(const float4*)&g_h2[((size_t)img * CH + k) * HW + hw0 + c4 * 4];
            *(float4*)(smem + C3_F_OFF + k * 256 + ((c4 ^ (k & 15)) * 16)) = v4;
        }
        __syncthreads();

        // ---- convert to bf16x3 [split][kh][px][64k] (144B stride) ----
        {
            int px = tid & 63, kg = tid >> 6;    // kg 0..3
            u32 pr0 = 0, pr1 = 0, pr2 = 0;
#pragma unroll
            for (int i = 0; i < 32; i++) {
                int k = kg * 32 + i;
                float h = *(const float*)(smem + C3_F_OFF + k * 256 +
                                          (((px >> 2) ^ (k & 15)) * 16) + (px & 3) * 4);
                __nv_bfloat16 c0 = __float2bfloat16_rn(h);
                float r1 = h - __bfloat162float(c0);
                __nv_bfloat16 c1 = __float2bfloat16_rn(r1);
                float r2 = r1 - __bfloat162float(c1);
                __nv_bfloat16 c2 = __float2bfloat16_rn(r2);
                if ((i & 1) == 0) {
                    pr0 = *(u16*)&c0; pr1 = *(u16*)&c1; pr2 = *(u16*)&c2;
                } else {
                    int kh = k >> 6, ko = (k & 63) - 1;
                    u32 base = C3_B_OFF + kh * C3_B_KH + px * BSTR + ko * 2;
                    *(u32*)(smem + base)                  = pr0 | ((u32)*(u16*)&c0 << 16);
                    *(u32*)(smem + base + C3_B_SPLIT)     = pr1 | ((u32)*(u16*)&c1 << 16);
                    *(u32*)(smem + base + 2 * C3_B_SPLIT) = pr2 | ((u32)*(u16*)&c2 << 16);
                }
            }
        }
        if (t == 0) cp_wait0();    // A tiles arrived
        __syncthreads();

        // ---- MMA: 6 combos x 8 ksteps ----
        float acc[2][4][4];
#pragma unroll
        for (int a = 0; a < 2; a++)
#pragma unroll
            for (int n = 0; n < 4; n++)
#pragma unroll
                for (int d = 0; d < 4; d++) acc[a][n][d] = 0.f;

#pragma unroll 1
        for (int c = 0; c < 6; c++) {
            const int ai = AI[c], bj = BJ[c];
#pragma unroll
            for (int kh = 0; kh < 2; kh++) {
#pragma unroll
                for (int ks = 0; ks < 4; ks++) {
                    u32 afr[2][4];
                    u32 ab = sb + ai * C3_A_SPLIT + kh * C3_A_KH + (u32)(m0 * BSTR)
                             + aLane + ks * 32;
                    ldm4(afr[0], ab);
                    ldm4(afr[1], ab + 16 * BSTR);
#pragma unroll
                    for (int nt = 0; nt < 4; nt++) {
                        u32 bfr[2];
                        ldm2(bfr, sb + C3_B_OFF + bj * C3_B_SPLIT + kh * C3_B_KH
                                  + (u32)((n0 + nt * 8) * BSTR) + bLane + ks * 32);
                        mma16816(acc[0][nt], afr[0], bfr);
                        mma16816(acc[1][nt], afr[1], bfr);
                    }
                }
            }
        }

        // ---- epilogue: BN + LIF + store spikes ----
#pragma unroll
        for (int nt = 0; nt < 4; nt++) {
            int n = n0 + nt * 8 + 2 * t2;
#pragma unroll
            for (int mt = 0; mt < 2; mt++) {
                int clo = cb * 128 + m0 + mt * 16 + g;
                float s[4];
#pragma unroll
                for (int d = 0; d < 4; d++) {
                    int h = d >> 1;
                    float h3 = acc[mt][nt][d] * scv[mt][h] + biv[mt][h];
                    float v = vst[mt][nt][d];
                    v = v + (h3 - v) * 0.5f;
                    float sp = (v >= 1.0f) ? 1.0f : 0.0f;
                    s[d] = sp;
                    vst[mt][nt][d] = v * (1.0f - sp);
                }
                *(float2*)&out[((size_t)img * COUT + clo) * HW + hw0 + n] =
                    make_float2(s[0], s[1]);
                *(float2*)&out[((size_t)img * COUT + clo + 8) * HW + hw0 + n] =
                    make_float2(s[2], s[3]);
            }
        }
    }
}

// ---------------------------------------------------------------------------
extern "C" void kernel_launch(void* const* d_in, const int* in_sizes, int n_in,
                              void* d_out, int out_size)
{
    const float* x  = (const float*)d_in[0];
    const float* w1 = (const float*)d_in[1];
    const float* g1 = (const float*)d_in[2];
    const float* b1 = (const float*)d_in[3];
    const float* m1 = (const float*)d_in[4];
    const float* v1 = (const float*)d_in[5];
    const float* w2 = (const float*)d_in[6];
    const float* g2 = (const float*)d_in[7];
    const float* b2 = (const float*)d_in[8];
    const float* m2 = (const float*)d_in[9];
    const float* v2 = (const float*)d_in[10];
    const float* w3 = (const float*)d_in[11];
    const float* g3 = (const float*)d_in[12];
    const float* b3 = (const float*)d_in[13];
    const float* m3 = (const float*)d_in[14];
    const float* v3 = (const float*)d_in[15];
    float* out = (float*)d_out;

    cudaFuncSetAttribute(conv2_hmma_kernel,
                         cudaFuncAttributeMaxDynamicSharedMemorySize, SMEM_CONV2);
    cudaFuncSetAttribute(conv3_lif_kernel,
                         cudaFuncAttributeMaxDynamicSharedMemorySize, SMEM_CONV3);

    // weight splits
    prep_w2a_kernel<<<(9 * 128 * 128 + 255) / 256, 256>>>(w2);
    prep_w3s_kernel<<<(256 * 128 + 255) / 256, 256>>>(w3);

    // conv1: 1x1 256->128 + BN1 -> bf16x3 channel-last splits
    conv1_kernel<<<dim3(25, NIMG), 256>>>(w1, x, g1, b1, m1, v1);

    // conv2: 3x3 128->128 + BN2 via mma.sync -> g_h2 fp32
    conv2_hmma_kernel<<<dim3(28, NIMG), 256, SMEM_CONV2>>>(g2, b2, m2, v2);

    // conv3 + BN3 + LIF fused -> d_out spikes
    conv3_lif_kernel<<<dim3(49, BATCH, 2), 256, SMEM_CONV3>>>(g3, b3, m3, v3, out);
}